// round 3
// baseline (speedup 1.0000x reference)
#include <cuda_runtime.h>

#define BB 4
#define DD 128
#define HH 192
#define WW 192
#define HW (HH*WW)          // 36864
#define BHW (BB*HW)         // 147456
#define VOL ((size_t)DD*HW) // 4718592 per batch

// out layout: [x_2d | x_warp | y]
#define OFF_XWARP ((size_t)BHW)
#define OFF_Y     ((size_t)BHW + (size_t)BB*VOL)

// Per-batch 3x3 rotation (row-major) + translation (3): 12 floats
__device__ float g_mat[BB][12];

__global__ void setup_kernel(const float* __restrict__ rot0,
                             const float* __restrict__ rot1,
                             const float* __restrict__ rot2,
                             const float* __restrict__ tr1,
                             const float* __restrict__ tr2,
                             const float* __restrict__ cp) {
    int b = threadIdx.x;
    if (b >= BB) return;
    float az = rot0[b], ay = rot1[b], ax = rot2[b];
    float cz, sz, cy, sy, cx, sx;
    sincosf(az, &sz, &cz);
    sincosf(ay, &sy, &cy);
    sincosf(ax, &sx, &cx);
    // rot = Z @ Y @ X
    float R0 = cz*cy;
    float R1 = -sz*cx + cz*sy*sx;
    float R2 =  sz*sx + cz*sy*cx;
    float R3 = sz*cy;
    float R4 =  cz*cx + sz*sy*sx;
    float R5 = -cz*sx + sz*sy*cx;
    float R6 = -sy;
    float R7 = cy*sx;
    float R8 = cy*cx;
    float t0 = 0.0f;
    float t1 = tr1[b] * (float)HH;
    float t2 = tr2[b] * (float)WW;
    float c0 = cp[b*3+0], c1 = cp[b*3+1], c2 = cp[b*3+2];
    // mat = T(+c) @ [R|t] @ T(-c)  ->  R unchanged, t' = t - R*c + c
    float f0 = t0 - (R0*c0 + R1*c1 + R2*c2) + c0;
    float f1 = t1 - (R3*c0 + R4*c1 + R5*c2) + c1;
    float f2 = t2 - (R6*c0 + R7*c1 + R8*c2) + c2;
    g_mat[b][0]=R0; g_mat[b][1]=R1; g_mat[b][2]=R2;
    g_mat[b][3]=R3; g_mat[b][4]=R4; g_mat[b][5]=R5;
    g_mat[b][6]=R6; g_mat[b][7]=R7; g_mat[b][8]=R8;
    g_mat[b][9]=f0; g_mat[b][10]=f1; g_mat[b][11]=f2;
}

#define UNR 4

__global__ __launch_bounds__(256, 3)
void warp_kernel(const float* __restrict__ x,
                 const float* __restrict__ y,
                 float* __restrict__ out) {
    int idx = blockIdx.x * blockDim.x + threadIdx.x;
    if (idx >= BHW) return;
    int b  = idx / HW;
    int hw = idx - b * HW;
    int h  = hw / WW;
    int w  = hw - h * WW;

    const float* M = g_mat[b];
    float fh = (float)h, fw = (float)w;
    float gz0 = fmaf(M[1], fh, fmaf(M[2], fw, M[9]));
    float gy0 = fmaf(M[4], fh, fmaf(M[5], fw, M[10]));
    float gx0 = fmaf(M[7], fh, fmaf(M[8], fw, M[11]));
    float sz = M[0], sy = M[3], sx = M[6];   // per-d step = R column 0

    const float* __restrict__ vol = x + (size_t)b * VOL;
    float* __restrict__ outw = out + OFF_XWARP + (size_t)b * VOL + (size_t)hw;

    float sum = 0.0f;

    // Whole-column interior test: g is linear in d, extrema at endpoints.
    // Margin 1e-3 guards fma rounding drift.
    float fB = (float)(DD - 1);
    float gzB = fmaf(fB, sz, gz0);
    float gyB = fmaf(fB, sy, gy0);
    float gxB = fmaf(fB, sx, gx0);
    bool fast =
        gz0 >= 0.001f && gz0 < 126.999f && gzB >= 0.001f && gzB < 126.999f &&
        gy0 >= 0.001f && gy0 < 190.999f && gyB >= 0.001f && gyB < 190.999f &&
        gx0 >= 0.001f && gx0 < 190.999f && gxB >= 0.001f && gxB < 190.999f;

    if (fast) {
        for (int j0 = 0; j0 < DD; j0 += UNR) {
            float v[UNR][8];
            float rz[UNR], ry[UNR], rx[UNR];

            // Phase 1: indices + all loads batched (32 LDGs in flight)
            #pragma unroll
            for (int u = 0; u < UNR; ++u) {
                float fd = (float)(j0 + u);
                float gz = fmaf(fd, sz, gz0);
                float gy = fmaf(fd, sy, gy0);
                float gx = fmaf(fd, sx, gx0);
                int iz = (int)gz;      // g >= 0 -> trunc == floor
                int iy = (int)gy;
                int ix = (int)gx;
                rz[u] = gz - (float)iz;
                ry[u] = gy - (float)iy;
                rx[u] = gx - (float)ix;
                const float* p = vol + iz * HW + iy * WW + ix;
                v[u][0] = p[0];
                v[u][1] = p[1];
                v[u][2] = p[WW];
                v[u][3] = p[WW + 1];
                v[u][4] = p[HW];
                v[u][5] = p[HW + 1];
                v[u][6] = p[HW + WW];
                v[u][7] = p[HW + WW + 1];
            }

            // Phase 2: interpolation + stores
            #pragma unroll
            for (int u = 0; u < UNR; ++u) {
                float wx0 = 1.0f - rx[u];
                float wy0 = 1.0f - ry[u];
                float wz0 = 1.0f - rz[u];
                float a00 = fmaf(v[u][1], rx[u], v[u][0] * wx0);
                float a01 = fmaf(v[u][3], rx[u], v[u][2] * wx0);
                float a10 = fmaf(v[u][5], rx[u], v[u][4] * wx0);
                float a11 = fmaf(v[u][7], rx[u], v[u][6] * wx0);
                float b0  = fmaf(a01, ry[u], a00 * wy0);
                float b1  = fmaf(a11, ry[u], a10 * wy0);
                float val = fmaf(b1,  rz[u], b0  * wz0);
                outw[(size_t)(j0 + u) * HW] = val;
                sum += val;
            }
        }
    } else {
        for (int j = 0; j < DD; ++j) {
            float fd = (float)j;
            float gz = fmaf(fd, sz, gz0);
            float gy = fmaf(fd, sy, gy0);
            float gx = fmaf(fd, sx, gx0);

            float fz = floorf(gz), fy = floorf(gy), fx = floorf(gx);
            int iz = (int)fz, iy = (int)fy, ix = (int)fx;
            float rz = gz - fz, ry = gy - fy, rx = gx - fx;

            int iz1 = iz + 1, iy1 = iy + 1, ix1 = ix + 1;
            bool vz0 = (iz  >= 0) & (iz  < DD);
            bool vz1 = (iz1 >= 0) & (iz1 < DD);
            bool vy0 = (iy  >= 0) & (iy  < HH);
            bool vy1 = (iy1 >= 0) & (iy1 < HH);
            bool vx0 = (ix  >= 0) & (ix  < WW);
            bool vx1 = (ix1 >= 0) & (ix1 < WW);

            int z0c = min(max(iz , 0), DD-1);
            int z1c = min(max(iz1, 0), DD-1);
            int y0c = min(max(iy , 0), HH-1);
            int y1c = min(max(iy1, 0), HH-1);
            int x0c = min(max(ix , 0), WW-1);
            int x1c = min(max(ix1, 0), WW-1);

            const float* p00 = vol + ((size_t)z0c * HH + y0c) * WW;
            const float* p01 = vol + ((size_t)z0c * HH + y1c) * WW;
            const float* p10 = vol + ((size_t)z1c * HH + y0c) * WW;
            const float* p11 = vol + ((size_t)z1c * HH + y1c) * WW;

            float v000 = (vz0 & vy0 & vx0) ? p00[x0c] : 0.0f;
            float v001 = (vz0 & vy0 & vx1) ? p00[x1c] : 0.0f;
            float v010 = (vz0 & vy1 & vx0) ? p01[x0c] : 0.0f;
            float v011 = (vz0 & vy1 & vx1) ? p01[x1c] : 0.0f;
            float v100 = (vz1 & vy0 & vx0) ? p10[x0c] : 0.0f;
            float v101 = (vz1 & vy0 & vx1) ? p10[x1c] : 0.0f;
            float v110 = (vz1 & vy1 & vx0) ? p11[x0c] : 0.0f;
            float v111 = (vz1 & vy1 & vx1) ? p11[x1c] : 0.0f;

            float wx0 = 1.0f - rx;
            float wy0 = 1.0f - ry;
            float wz0 = 1.0f - rz;

            float a00 = fmaf(v001, rx, v000 * wx0);
            float a01 = fmaf(v011, rx, v010 * wx0);
            float a10 = fmaf(v101, rx, v100 * wx0);
            float a11 = fmaf(v111, rx, v110 * wx0);
            float b0  = fmaf(a01, ry, a00 * wy0);
            float b1  = fmaf(a11, ry, a10 * wy0);
            float val = fmaf(b1,  rz, b0  * wz0);

            outw[(size_t)j * HW] = val;
            sum += val;
        }
    }

    out[idx] = sum * (1.0f / (float)DD);       // x_2d
    out[OFF_Y + idx] = y[idx];                  // y passthrough
}

extern "C" void kernel_launch(void* const* d_in, const int* in_sizes, int n_in,
                              void* d_out, int out_size) {
    const float* x    = (const float*)d_in[0];
    const float* y    = (const float*)d_in[1];
    const float* rot0 = (const float*)d_in[2];
    const float* rot1 = (const float*)d_in[3];
    const float* rot2 = (const float*)d_in[4];
    const float* tr1  = (const float*)d_in[5];
    const float* tr2  = (const float*)d_in[6];
    const float* cp   = (const float*)d_in[7];
    float* out = (float*)d_out;

    setup_kernel<<<1, 32>>>(rot0, rot1, rot2, tr1, tr2, cp);
    warp_kernel<<<(BHW + 255) / 256, 256>>>(x, y, out);
}

// round 4
// speedup vs baseline: 1.0176x; 1.0176x over previous
#include <cuda_runtime.h>

#define BB 4
#define DD 128
#define HH 192
#define WW 192
#define HW (HH*WW)          // 36864
#define BHW (BB*HW)         // 147456
#define VOL ((size_t)DD*HW) // 4718592 per batch

// out layout: [x_2d | x_warp | y]
#define OFF_XWARP ((size_t)BHW)
#define OFF_Y     ((size_t)BHW + (size_t)BB*VOL)

// Per-batch 3x3 rotation (row-major) + translation (3): 12 floats
__device__ float g_mat[BB][12];

__global__ void setup_kernel(const float* __restrict__ rot0,
                             const float* __restrict__ rot1,
                             const float* __restrict__ rot2,
                             const float* __restrict__ tr1,
                             const float* __restrict__ tr2,
                             const float* __restrict__ cp) {
    int b = threadIdx.x;
    if (b >= BB) return;
    float az = rot0[b], ay = rot1[b], ax = rot2[b];
    float cz, sz, cy, sy, cx, sx;
    sincosf(az, &sz, &cz);
    sincosf(ay, &sy, &cy);
    sincosf(ax, &sx, &cx);
    // rot = Z @ Y @ X
    float R0 = cz*cy;
    float R1 = -sz*cx + cz*sy*sx;
    float R2 =  sz*sx + cz*sy*cx;
    float R3 = sz*cy;
    float R4 =  cz*cx + sz*sy*sx;
    float R5 = -cz*sx + sz*sy*cx;
    float R6 = -sy;
    float R7 = cy*sx;
    float R8 = cy*cx;
    float t0 = 0.0f;
    float t1 = tr1[b] * (float)HH;
    float t2 = tr2[b] * (float)WW;
    float c0 = cp[b*3+0], c1 = cp[b*3+1], c2 = cp[b*3+2];
    // mat = T(+c) @ [R|t] @ T(-c)  ->  R unchanged, t' = t - R*c + c
    float f0 = t0 - (R0*c0 + R1*c1 + R2*c2) + c0;
    float f1 = t1 - (R3*c0 + R4*c1 + R5*c2) + c1;
    float f2 = t2 - (R6*c0 + R7*c1 + R8*c2) + c2;
    g_mat[b][0]=R0; g_mat[b][1]=R1; g_mat[b][2]=R2;
    g_mat[b][3]=R3; g_mat[b][4]=R4; g_mat[b][5]=R5;
    g_mat[b][6]=R6; g_mat[b][7]=R7; g_mat[b][8]=R8;
    g_mat[b][9]=f0; g_mat[b][10]=f1; g_mat[b][11]=f2;
}

__global__ __launch_bounds__(256)
void warp_kernel(const float* __restrict__ x,
                 const float* __restrict__ y,
                 float* __restrict__ out) {
    int idx = blockIdx.x * blockDim.x + threadIdx.x;
    if (idx >= BHW) return;
    int b  = idx / HW;
    int hw = idx - b * HW;
    int h  = hw / WW;
    int w  = hw - h * WW;

    const float* M = g_mat[b];
    float fh = (float)h, fw = (float)w;
    float gz0 = fmaf(M[1], fh, fmaf(M[2], fw, M[9]));
    float gy0 = fmaf(M[4], fh, fmaf(M[5], fw, M[10]));
    float gx0 = fmaf(M[7], fh, fmaf(M[8], fw, M[11]));
    float sz = M[0], sy = M[3], sx = M[6];   // per-d step = R column 0

    const float* __restrict__ vol = x + (size_t)b * VOL;
    float* __restrict__ outw = out + OFF_XWARP + (size_t)b * VOL + (size_t)hw;

    float sum = 0.0f;

    // Whole-column interior test: g is linear in d, extrema at endpoints.
    float fB = (float)(DD - 1);
    float gzB = fmaf(fB, sz, gz0);
    float gyB = fmaf(fB, sy, gy0);
    float gxB = fmaf(fB, sx, gx0);
    bool fast =
        gz0 >= 0.001f && gz0 < 126.999f && gzB >= 0.001f && gzB < 126.999f &&
        gy0 >= 0.001f && gy0 < 190.999f && gyB >= 0.001f && gyB < 190.999f &&
        gx0 >= 0.001f && gx0 < 190.999f && gxB >= 0.001f && gxB < 190.999f;

    if (fast) {
        float fd = 0.0f;
        #pragma unroll 4
        for (int j = 0; j < DD; ++j) {
            float gz = fmaf(fd, sz, gz0);
            float gy = fmaf(fd, sy, gy0);
            float gx = fmaf(fd, sx, gx0);
            fd += 1.0f;

            int iz = (int)gz;            // interior -> trunc == floor
            int iy = (int)gy;
            int ix = (int)gx;
            float rz = gz - (float)iz;
            float ry = gy - (float)iy;
            float rx = gx - (float)ix;

            const float* p = vol + iz * HW + iy * WW + ix;
            float v000 = p[0];
            float v001 = p[1];
            float v010 = p[WW];
            float v011 = p[WW + 1];
            float v100 = p[HW];
            float v101 = p[HW + 1];
            float v110 = p[HW + WW];
            float v111 = p[HW + WW + 1];

            float wx0 = 1.0f - rx;
            float wy0 = 1.0f - ry;
            float wz0 = 1.0f - rz;

            float a00 = fmaf(v001, rx, v000 * wx0);
            float a01 = fmaf(v011, rx, v010 * wx0);
            float a10 = fmaf(v101, rx, v100 * wx0);
            float a11 = fmaf(v111, rx, v110 * wx0);
            float b0  = fmaf(a01, ry, a00 * wy0);
            float b1  = fmaf(a11, ry, a10 * wy0);
            float val = fmaf(b1,  rz, b0  * wz0);

            outw[(size_t)j * HW] = val;
            sum += val;
        }
    } else {
        for (int j = 0; j < DD; ++j) {
            float fd = (float)j;
            float gz = fmaf(fd, sz, gz0);
            float gy = fmaf(fd, sy, gy0);
            float gx = fmaf(fd, sx, gx0);

            float fz = floorf(gz), fy = floorf(gy), fx = floorf(gx);
            int iz = (int)fz, iy = (int)fy, ix = (int)fx;
            float rz = gz - fz, ry = gy - fy, rx = gx - fx;

            int iz1 = iz + 1, iy1 = iy + 1, ix1 = ix + 1;
            bool vz0 = (iz  >= 0) & (iz  < DD);
            bool vz1 = (iz1 >= 0) & (iz1 < DD);
            bool vy0 = (iy  >= 0) & (iy  < HH);
            bool vy1 = (iy1 >= 0) & (iy1 < HH);
            bool vx0 = (ix  >= 0) & (ix  < WW);
            bool vx1 = (ix1 >= 0) & (ix1 < WW);

            int z0c = min(max(iz , 0), DD-1);
            int z1c = min(max(iz1, 0), DD-1);
            int y0c = min(max(iy , 0), HH-1);
            int y1c = min(max(iy1, 0), HH-1);
            int x0c = min(max(ix , 0), WW-1);
            int x1c = min(max(ix1, 0), WW-1);

            const float* p00 = vol + ((size_t)z0c * HH + y0c) * WW;
            const float* p01 = vol + ((size_t)z0c * HH + y1c) * WW;
            const float* p10 = vol + ((size_t)z1c * HH + y0c) * WW;
            const float* p11 = vol + ((size_t)z1c * HH + y1c) * WW;

            float v000 = (vz0 & vy0 & vx0) ? p00[x0c] : 0.0f;
            float v001 = (vz0 & vy0 & vx1) ? p00[x1c] : 0.0f;
            float v010 = (vz0 & vy1 & vx0) ? p01[x0c] : 0.0f;
            float v011 = (vz0 & vy1 & vx1) ? p01[x1c] : 0.0f;
            float v100 = (vz1 & vy0 & vx0) ? p10[x0c] : 0.0f;
            float v101 = (vz1 & vy0 & vx1) ? p10[x1c] : 0.0f;
            float v110 = (vz1 & vy1 & vx0) ? p11[x0c] : 0.0f;
            float v111 = (vz1 & vy1 & vx1) ? p11[x1c] : 0.0f;

            float wx0 = 1.0f - rx;
            float wy0 = 1.0f - ry;
            float wz0 = 1.0f - rz;

            float a00 = fmaf(v001, rx, v000 * wx0);
            float a01 = fmaf(v011, rx, v010 * wx0);
            float a10 = fmaf(v101, rx, v100 * wx0);
            float a11 = fmaf(v111, rx, v110 * wx0);
            float b0  = fmaf(a01, ry, a00 * wy0);
            float b1  = fmaf(a11, ry, a10 * wy0);
            float val = fmaf(b1,  rz, b0  * wz0);

            outw[(size_t)j * HW] = val;
            sum += val;
        }
    }

    out[idx] = sum * (1.0f / (float)DD);       // x_2d
    out[OFF_Y + idx] = y[idx];                  // y passthrough
}

extern "C" void kernel_launch(void* const* d_in, const int* in_sizes, int n_in,
                              void* d_out, int out_size) {
    const float* x    = (const float*)d_in[0];
    const float* y    = (const float*)d_in[1];
    const float* rot0 = (const float*)d_in[2];
    const float* rot1 = (const float*)d_in[3];
    const float* rot2 = (const float*)d_in[4];
    const float* tr1  = (const float*)d_in[5];
    const float* tr2  = (const float*)d_in[6];
    const float* cp   = (const float*)d_in[7];
    float* out = (float*)d_out;

    setup_kernel<<<1, 32>>>(rot0, rot1, rot2, tr1, tr2, cp);
    warp_kernel<<<(BHW + 255) / 256, 256>>>(x, y, out);
}

// round 5
// speedup vs baseline: 1.7002x; 1.6708x over previous
#include <cuda_runtime.h>

#define BB 4
#define DD 128
#define HH 192
#define WW 192
#define HW (HH*WW)          // 36864
#define BHW (BB*HW)         // 147456
#define VOL ((size_t)DD*HW) // 4718592 per batch

#define DSPLIT 4
#define DCH (DD/DSPLIT)     // 32

// out layout: [x_2d | x_warp | y]
#define OFF_XWARP ((size_t)BHW)
#define OFF_Y     ((size_t)BHW + (size_t)BB*VOL)

__device__ float g_mat[BB][12];
__device__ float g_partial[DSPLIT * BHW];   // per-chunk partial sums

__global__ void setup_kernel(const float* __restrict__ rot0,
                             const float* __restrict__ rot1,
                             const float* __restrict__ rot2,
                             const float* __restrict__ tr1,
                             const float* __restrict__ tr2,
                             const float* __restrict__ cp) {
    int b = threadIdx.x;
    if (b >= BB) return;
    float az = rot0[b], ay = rot1[b], ax = rot2[b];
    float cz, sz, cy, sy, cx, sx;
    sincosf(az, &sz, &cz);
    sincosf(ay, &sy, &cy);
    sincosf(ax, &sx, &cx);
    float R0 = cz*cy;
    float R1 = -sz*cx + cz*sy*sx;
    float R2 =  sz*sx + cz*sy*cx;
    float R3 = sz*cy;
    float R4 =  cz*cx + sz*sy*sx;
    float R5 = -cz*sx + sz*sy*cx;
    float R6 = -sy;
    float R7 = cy*sx;
    float R8 = cy*cx;
    float t0 = 0.0f;
    float t1 = tr1[b] * (float)HH;
    float t2 = tr2[b] * (float)WW;
    float c0 = cp[b*3+0], c1 = cp[b*3+1], c2 = cp[b*3+2];
    float f0 = t0 - (R0*c0 + R1*c1 + R2*c2) + c0;
    float f1 = t1 - (R3*c0 + R4*c1 + R5*c2) + c1;
    float f2 = t2 - (R6*c0 + R7*c1 + R8*c2) + c2;
    g_mat[b][0]=R0; g_mat[b][1]=R1; g_mat[b][2]=R2;
    g_mat[b][3]=R3; g_mat[b][4]=R4; g_mat[b][5]=R5;
    g_mat[b][6]=R6; g_mat[b][7]=R7; g_mat[b][8]=R8;
    g_mat[b][9]=f0; g_mat[b][10]=f1; g_mat[b][11]=f2;
}

__device__ __forceinline__ float guarded_sample(const float* __restrict__ vol,
                                                float gz, float gy, float gx) {
    float fz = floorf(gz), fy = floorf(gy), fx = floorf(gx);
    int iz = (int)fz, iy = (int)fy, ix = (int)fx;
    float rz = gz - fz, ry = gy - fy, rx = gx - fx;

    int iz1 = iz + 1, iy1 = iy + 1, ix1 = ix + 1;
    bool vz0 = (iz  >= 0) & (iz  < DD);
    bool vz1 = (iz1 >= 0) & (iz1 < DD);
    bool vy0 = (iy  >= 0) & (iy  < HH);
    bool vy1 = (iy1 >= 0) & (iy1 < HH);
    bool vx0 = (ix  >= 0) & (ix  < WW);
    bool vx1 = (ix1 >= 0) & (ix1 < WW);

    int z0c = min(max(iz , 0), DD-1);
    int z1c = min(max(iz1, 0), DD-1);
    int y0c = min(max(iy , 0), HH-1);
    int y1c = min(max(iy1, 0), HH-1);
    int x0c = min(max(ix , 0), WW-1);
    int x1c = min(max(ix1, 0), WW-1);

    const float* p00 = vol + (z0c * HH + y0c) * WW;
    const float* p01 = vol + (z0c * HH + y1c) * WW;
    const float* p10 = vol + (z1c * HH + y0c) * WW;
    const float* p11 = vol + (z1c * HH + y1c) * WW;

    float v000 = (vz0 & vy0 & vx0) ? p00[x0c] : 0.0f;
    float v001 = (vz0 & vy0 & vx1) ? p00[x1c] : 0.0f;
    float v010 = (vz0 & vy1 & vx0) ? p01[x0c] : 0.0f;
    float v011 = (vz0 & vy1 & vx1) ? p01[x1c] : 0.0f;
    float v100 = (vz1 & vy0 & vx0) ? p10[x0c] : 0.0f;
    float v101 = (vz1 & vy0 & vx1) ? p10[x1c] : 0.0f;
    float v110 = (vz1 & vy1 & vx0) ? p11[x0c] : 0.0f;
    float v111 = (vz1 & vy1 & vx1) ? p11[x1c] : 0.0f;

    float wx0 = 1.0f - rx, wy0 = 1.0f - ry, wz0 = 1.0f - rz;
    float a00 = fmaf(v001, rx, v000 * wx0);
    float a01 = fmaf(v011, rx, v010 * wx0);
    float a10 = fmaf(v101, rx, v100 * wx0);
    float a11 = fmaf(v111, rx, v110 * wx0);
    float b0  = fmaf(a01, ry, a00 * wy0);
    float b1  = fmaf(a11, ry, a10 * wy0);
    return fmaf(b1, rz, b0 * wz0);
}

__global__ __launch_bounds__(256, 6)
void warp_kernel(const float* __restrict__ x, float* __restrict__ out) {
    int hw = blockIdx.x * blockDim.x + threadIdx.x;   // 0..HW-1
    int b  = blockIdx.y;                              // 0..BB-1
    int c  = blockIdx.z;                              // 0..DSPLIT-1
    int h  = hw / WW;
    int w  = hw - h * WW;
    int d0 = c * DCH;
    int dend = d0 + DCH;

    const float* M = g_mat[b];
    float fh = (float)h, fw = (float)w;
    float gz0 = fmaf(M[1], fh, fmaf(M[2], fw, M[9]));
    float gy0 = fmaf(M[4], fh, fmaf(M[5], fw, M[10]));
    float gx0 = fmaf(M[7], fh, fmaf(M[8], fw, M[11]));
    float sz = M[0], sy = M[3], sx = M[6];

    const float* __restrict__ vol = x + (size_t)b * VOL;
    float* __restrict__ outw = out + OFF_XWARP + (size_t)b * VOL + (size_t)hw;

    // z-interior d-window: gz(d) = gz0 + d*sz monotone increasing (sz ~ 0.95+)
    int flo = dend, fhi = dend;  // default: no fast region
    if (sz > 0.5f) {
        float inv = 1.0f / sz;
        int wlo = (int)ceilf((0.001f - gz0) * inv);
        int whi = (int)floorf((126.999f - gz0) * inv);
        flo = max(d0, wlo);
        fhi = min(dend, whi + 1);
        if (flo > fhi) { flo = dend; fhi = dend; }
    }

    // y/x interior over the fast window (linear -> endpoints)
    if (flo < fhi) {
        float fA = (float)flo, fB = (float)(fhi - 1);
        float gyA = fmaf(fA, sy, gy0), gyB = fmaf(fB, sy, gy0);
        float gxA = fmaf(fA, sx, gx0), gxB = fmaf(fB, sx, gx0);
        bool okyx =
            gyA >= 0.001f && gyA < 190.999f && gyB >= 0.001f && gyB < 190.999f &&
            gxA >= 0.001f && gxA < 190.999f && gxB >= 0.001f && gxB < 190.999f;
        if (!okyx) { flo = dend; fhi = dend; }
    }

    float sum = 0.0f;
    int j = d0;

    for (; j < flo; ++j) {   // pre-window guarded
        float fd = (float)j;
        float val = guarded_sample(vol,
            fmaf(fd, sz, gz0), fmaf(fd, sy, gy0), fmaf(fd, sx, gx0));
        outw[(size_t)j * HW] = val;
        sum += val;
    }

    #pragma unroll 4
    for (; j < fhi; ++j) {   // interior fast
        float fd = (float)j;
        float gz = fmaf(fd, sz, gz0);
        float gy = fmaf(fd, sy, gy0);
        float gx = fmaf(fd, sx, gx0);

        int iz = (int)gz;
        int iy = (int)gy;
        int ix = (int)gx;
        float rz = gz - (float)iz;
        float ry = gy - (float)iy;
        float rx = gx - (float)ix;

        const float* p = vol + iz * HW + iy * WW + ix;
        float v000 = p[0];
        float v001 = p[1];
        float v010 = p[WW];
        float v011 = p[WW + 1];
        float v100 = p[HW];
        float v101 = p[HW + 1];
        float v110 = p[HW + WW];
        float v111 = p[HW + WW + 1];

        float wx0 = 1.0f - rx, wy0 = 1.0f - ry, wz0 = 1.0f - rz;
        float a00 = fmaf(v001, rx, v000 * wx0);
        float a01 = fmaf(v011, rx, v010 * wx0);
        float a10 = fmaf(v101, rx, v100 * wx0);
        float a11 = fmaf(v111, rx, v110 * wx0);
        float b0  = fmaf(a01, ry, a00 * wy0);
        float b1  = fmaf(a11, ry, a10 * wy0);
        float val = fmaf(b1,  rz, b0  * wz0);

        outw[(size_t)j * HW] = val;
        sum += val;
    }

    for (; j < dend; ++j) {  // post-window guarded
        float fd = (float)j;
        float val = guarded_sample(vol,
            fmaf(fd, sz, gz0), fmaf(fd, sy, gy0), fmaf(fd, sx, gx0));
        outw[(size_t)j * HW] = val;
        sum += val;
    }

    g_partial[(c * BB + b) * HW + hw] = sum;
}

// x_2d = mean of partials; y passthrough.
__global__ __launch_bounds__(256)
void reduce_kernel(const float* __restrict__ y, float* __restrict__ out) {
    int i = blockIdx.x * blockDim.x + threadIdx.x;
    if (i >= BHW) return;
    int b  = i / HW;
    int hw = i - b * HW;
    float s = 0.0f;
    #pragma unroll
    for (int c = 0; c < DSPLIT; ++c)
        s += g_partial[(c * BB + b) * HW + hw];
    out[i] = s * (1.0f / (float)DD);
    out[OFF_Y + i] = y[i];
}

extern "C" void kernel_launch(void* const* d_in, const int* in_sizes, int n_in,
                              void* d_out, int out_size) {
    const float* x    = (const float*)d_in[0];
    const float* y    = (const float*)d_in[1];
    const float* rot0 = (const float*)d_in[2];
    const float* rot1 = (const float*)d_in[3];
    const float* rot2 = (const float*)d_in[4];
    const float* tr1  = (const float*)d_in[5];
    const float* tr2  = (const float*)d_in[6];
    const float* cp   = (const float*)d_in[7];
    float* out = (float*)d_out;

    setup_kernel<<<1, 32>>>(rot0, rot1, rot2, tr1, tr2, cp);
    dim3 grid(HW / 256, BB, DSPLIT);
    warp_kernel<<<grid, 256>>>(x, out);
    reduce_kernel<<<(BHW + 255) / 256, 256>>>(y, out);
}

// round 7
// speedup vs baseline: 1.7338x; 1.0198x over previous
#include <cuda_runtime.h>

#define BB 4
#define DD 128
#define HH 192
#define WW 192
#define HW (HH*WW)          // 36864
#define BHW (BB*HW)         // 147456
#define VOL ((size_t)DD*HW) // 4718592 per batch

#define DSPLIT 4
#define DCH (DD/DSPLIT)     // 32

// out layout: [x_2d | x_warp | y]
#define OFF_XWARP ((size_t)BHW)
#define OFF_Y     ((size_t)BHW + (size_t)BB*VOL)

__device__ float g_partial[DSPLIT * BHW];   // per-chunk partial sums

// Guarded trilinear sample with border handling (zero outside).
__device__ __forceinline__ float guarded_sample(const float* __restrict__ vol,
                                                float gz, float gy, float gx) {
    float fz = floorf(gz), fy = floorf(gy), fx = floorf(gx);
    int iz = (int)fz, iy = (int)fy, ix = (int)fx;
    float rz = gz - fz, ry = gy - fy, rx = gx - fx;

    int iz1 = iz + 1, iy1 = iy + 1, ix1 = ix + 1;
    bool vz0 = (iz  >= 0) & (iz  < DD);
    bool vz1 = (iz1 >= 0) & (iz1 < DD);
    bool vy0 = (iy  >= 0) & (iy  < HH);
    bool vy1 = (iy1 >= 0) & (iy1 < HH);
    bool vx0 = (ix  >= 0) & (ix  < WW);
    bool vx1 = (ix1 >= 0) & (ix1 < WW);

    int z0c = min(max(iz , 0), DD-1);
    int z1c = min(max(iz1, 0), DD-1);
    int y0c = min(max(iy , 0), HH-1);
    int y1c = min(max(iy1, 0), HH-1);
    int x0c = min(max(ix , 0), WW-1);
    int x1c = min(max(ix1, 0), WW-1);

    const float* p00 = vol + (z0c * HH + y0c) * WW;
    const float* p01 = vol + (z0c * HH + y1c) * WW;
    const float* p10 = vol + (z1c * HH + y0c) * WW;
    const float* p11 = vol + (z1c * HH + y1c) * WW;

    float v000 = (vz0 & vy0 & vx0) ? p00[x0c] : 0.0f;
    float v001 = (vz0 & vy0 & vx1) ? p00[x1c] : 0.0f;
    float v010 = (vz0 & vy1 & vx0) ? p01[x0c] : 0.0f;
    float v011 = (vz0 & vy1 & vx1) ? p01[x1c] : 0.0f;
    float v100 = (vz1 & vy0 & vx0) ? p10[x0c] : 0.0f;
    float v101 = (vz1 & vy0 & vx1) ? p10[x1c] : 0.0f;
    float v110 = (vz1 & vy1 & vx0) ? p11[x0c] : 0.0f;
    float v111 = (vz1 & vy1 & vx1) ? p11[x1c] : 0.0f;

    float wx0 = 1.0f - rx, wy0 = 1.0f - ry, wz0 = 1.0f - rz;
    float a00 = fmaf(v001, rx, v000 * wx0);
    float a01 = fmaf(v011, rx, v010 * wx0);
    float a10 = fmaf(v101, rx, v100 * wx0);
    float a11 = fmaf(v111, rx, v100 * 0.0f + v100 * 0.0f + v110 * wx0); // placeholder removed below
    // NOTE: see corrected tree below
    a11 = fmaf(v111, rx, v110 * wx0);
    float b0  = fmaf(a01, ry, a00 * wy0);
    float b1  = fmaf(a11, ry, a10 * wy0);
    return fmaf(b1, rz, b0 * wz0);
}

// Shrink [lo,hi] (float d-range) to where g0 + s*d stays in
// (0.001, bound-1-0.001): both floor and floor+1 strictly interior.
__device__ __forceinline__ void axis_window(float g0, float s, float bound,
                                            float& lo, float& hi) {
    float upper = bound - 1.001f;
    if (fabsf(s) < 1e-6f) {
        if (!(g0 >= 0.001f && g0 <= upper)) { lo = 1e9f; hi = -1e9f; }
    } else {
        float inv = 1.0f / s;
        float a = (0.001f - g0) * inv;
        float b = (upper - g0) * inv;
        lo = fmaxf(lo, fminf(a, b));
        hi = fminf(hi, fmaxf(a, b));
    }
}

__global__ __launch_bounds__(256, 6)
void warp_kernel(const float* __restrict__ x,
                 const float* __restrict__ rot0, const float* __restrict__ rot1,
                 const float* __restrict__ rot2, const float* __restrict__ tr1,
                 const float* __restrict__ tr2,  const float* __restrict__ cp,
                 float* __restrict__ out) {
    __shared__ float M[12];
    int b  = blockIdx.y;                              // 0..BB-1
    int c  = blockIdx.z;                              // 0..DSPLIT-1

    if (threadIdx.x == 0) {
        float az = rot0[b], ay = rot1[b], ax = rot2[b];
        float cz, szs, cy, sys, cx, sxs;
        sincosf(az, &szs, &cz);
        sincosf(ay, &sys, &cy);
        sincosf(ax, &sxs, &cx);
        float R0 = cz*cy;
        float R1 = -szs*cx + cz*sys*sxs;
        float R2 =  szs*sxs + cz*sys*cx;
        float R3 = szs*cy;
        float R4 =  cz*cx + szs*sys*sxs;
        float R5 = -cz*sxs + szs*sys*cx;
        float R6 = -sys;
        float R7 = cy*sxs;
        float R8 = cy*cx;
        float t1 = tr1[b] * (float)HH;
        float t2 = tr2[b] * (float)WW;
        float c0 = cp[b*3+0], c1 = cp[b*3+1], c2 = cp[b*3+2];
        M[0]=R0; M[1]=R1; M[2]=R2;
        M[3]=R3; M[4]=R4; M[5]=R5;
        M[6]=R6; M[7]=R7; M[8]=R8;
        M[9]  = 0.0f - (R0*c0 + R1*c1 + R2*c2) + c0;
        M[10] = t1   - (R3*c0 + R4*c1 + R5*c2) + c1;
        M[11] = t2   - (R6*c0 + R7*c1 + R8*c2) + c2;
    }
    __syncthreads();

    int hw = blockIdx.x * blockDim.x + threadIdx.x;   // 0..HW-1
    int h  = hw / WW;
    int w  = hw - h * WW;
    int d0 = c * DCH;
    int dend = d0 + DCH;

    float fh = (float)h, fw = (float)w;
    float gz0 = fmaf(M[1], fh, fmaf(M[2], fw, M[9]));
    float gy0 = fmaf(M[4], fh, fmaf(M[5], fw, M[10]));
    float gx0 = fmaf(M[7], fh, fmaf(M[8], fw, M[11]));
    float sz = M[0], sy = M[3], sx = M[6];

    const float* __restrict__ vol = x + (size_t)b * VOL;
    float* __restrict__ outw = out + OFF_XWARP + (size_t)b * VOL + (size_t)hw;

    // Exact interior d-window: intersection of three per-axis intervals.
    float wlo = (float)d0, whi = (float)(dend - 1);
    axis_window(gz0, sz, (float)DD, wlo, whi);
    axis_window(gy0, sy, (float)HH, wlo, whi);
    axis_window(gx0, sx, (float)WW, wlo, whi);

    int flo, fhi;
    if (wlo > whi) { flo = dend; fhi = dend; }
    else {
        flo = max(d0,   (int)ceilf(wlo));
        fhi = min(dend, (int)floorf(whi) + 1);
        if (flo > fhi) { flo = dend; fhi = dend; }
    }

    float sum = 0.0f;
    int j = d0;

    for (; j < flo; ++j) {   // pre-window guarded (boundary band only)
        float fd = (float)j;
        float val = guarded_sample(vol,
            fmaf(fd, sz, gz0), fmaf(fd, sy, gy0), fmaf(fd, sx, gx0));
        outw[(size_t)j * HW] = val;
        sum += val;
    }

    #pragma unroll 4
    for (; j < fhi; ++j) {   // interior fast
        float fd = (float)j;
        float gz = fmaf(fd, sz, gz0);
        float gy = fmaf(fd, sy, gy0);
        float gx = fmaf(fd, sx, gx0);

        int iz = (int)gz;
        int iy = (int)gy;
        int ix = (int)gx;
        float rz = gz - (float)iz;
        float ry = gy - (float)iy;
        float rx = gx - (float)ix;

        const float* p = vol + iz * HW + iy * WW + ix;
        float v000 = p[0];
        float v001 = p[1];
        float v010 = p[WW];
        float v011 = p[WW + 1];
        float v100 = p[HW];
        float v101 = p[HW + 1];
        float v110 = p[HW + WW];
        float v111 = p[HW + WW + 1];

        float wx0 = 1.0f - rx, wy0 = 1.0f - ry, wz0 = 1.0f - rz;
        float a00 = fmaf(v001, rx, v000 * wx0);
        float a01 = fmaf(v011, rx, v010 * wx0);
        float a10 = fmaf(v101, rx, v100 * wx0);
        float a11 = fmaf(v111, rx, v110 * wx0);
        float b0  = fmaf(a01, ry, a00 * wy0);
        float b1  = fmaf(a11, ry, a10 * wy0);
        float val = fmaf(b1,  rz, b0  * wz0);

        outw[(size_t)j * HW] = val;
        sum += val;
    }

    for (; j < dend; ++j) {  // post-window guarded
        float fd = (float)j;
        float val = guarded_sample(vol,
            fmaf(fd, sz, gz0), fmaf(fd, sy, gy0), fmaf(fd, sx, gx0));
        outw[(size_t)j * HW] = val;
        sum += val;
    }

    g_partial[(c * BB + b) * HW + hw] = sum;
}

// x_2d = mean of partials; y passthrough.
__global__ __launch_bounds__(256)
void reduce_kernel(const float* __restrict__ y, float* __restrict__ out) {
    int i = blockIdx.x * blockDim.x + threadIdx.x;
    if (i >= BHW) return;
    int b  = i / HW;
    int hw = i - b * HW;
    float s = 0.0f;
    #pragma unroll
    for (int c = 0; c < DSPLIT; ++c)
        s += g_partial[(c * BB + b) * HW + hw];
    out[i] = s * (1.0f / (float)DD);
    out[OFF_Y + i] = y[i];
}

extern "C" void kernel_launch(void* const* d_in, const int* in_sizes, int n_in,
                              void* d_out, int out_size) {
    const float* x    = (const float*)d_in[0];
    const float* y    = (const float*)d_in[1];
    const float* rot0 = (const float*)d_in[2];
    const float* rot1 = (const float*)d_in[3];
    const float* rot2 = (const float*)d_in[4];
    const float* tr1  = (const float*)d_in[5];
    const float* tr2  = (const float*)d_in[6];
    const float* cp   = (const float*)d_in[7];
    float* out = (float*)d_out;

    dim3 grid(HW / 256, BB, DSPLIT);
    warp_kernel<<<grid, 256>>>(x, rot0, rot1, rot2, tr1, tr2, cp, out);
    reduce_kernel<<<(BHW + 255) / 256, 256>>>(y, out);
}

// round 8
// speedup vs baseline: 1.7711x; 1.0215x over previous
#include <cuda_runtime.h>

#define BB 4
#define DD 128
#define HH 192
#define WW 192
#define HW (HH*WW)          // 36864
#define BHW (BB*HW)         // 147456
#define VOL ((size_t)DD*HW) // 4718592 per batch

#define DSPLIT 4
#define DCH (DD/DSPLIT)     // 32

// out layout: [x_2d | x_warp | y]
#define OFF_XWARP ((size_t)BHW)
#define OFF_Y     ((size_t)BHW + (size_t)BB*VOL)

__device__ float g_partial[DSPLIT * BHW];   // per-chunk partial sums

// Guarded trilinear sample with border handling (zero outside).
__device__ __forceinline__ float guarded_sample(const float* __restrict__ vol,
                                                float gz, float gy, float gx) {
    float fz = floorf(gz), fy = floorf(gy), fx = floorf(gx);
    int iz = (int)fz, iy = (int)fy, ix = (int)fx;
    float rz = gz - fz, ry = gy - fy, rx = gx - fx;

    int iz1 = iz + 1, iy1 = iy + 1, ix1 = ix + 1;
    bool vz0 = (iz  >= 0) & (iz  < DD);
    bool vz1 = (iz1 >= 0) & (iz1 < DD);
    bool vy0 = (iy  >= 0) & (iy  < HH);
    bool vy1 = (iy1 >= 0) & (iy1 < HH);
    bool vx0 = (ix  >= 0) & (ix  < WW);
    bool vx1 = (ix1 >= 0) & (ix1 < WW);

    int z0c = min(max(iz , 0), DD-1);
    int z1c = min(max(iz1, 0), DD-1);
    int y0c = min(max(iy , 0), HH-1);
    int y1c = min(max(iy1, 0), HH-1);
    int x0c = min(max(ix , 0), WW-1);
    int x1c = min(max(ix1, 0), WW-1);

    const float* p00 = vol + (z0c * HH + y0c) * WW;
    const float* p01 = vol + (z0c * HH + y1c) * WW;
    const float* p10 = vol + (z1c * HH + y0c) * WW;
    const float* p11 = vol + (z1c * HH + y1c) * WW;

    float v000 = (vz0 & vy0 & vx0) ? p00[x0c] : 0.0f;
    float v001 = (vz0 & vy0 & vx1) ? p00[x1c] : 0.0f;
    float v010 = (vz0 & vy1 & vx0) ? p01[x0c] : 0.0f;
    float v011 = (vz0 & vy1 & vx1) ? p01[x1c] : 0.0f;
    float v100 = (vz1 & vy0 & vx0) ? p10[x0c] : 0.0f;
    float v101 = (vz1 & vy0 & vx1) ? p10[x1c] : 0.0f;
    float v110 = (vz1 & vy1 & vx0) ? p11[x0c] : 0.0f;
    float v111 = (vz1 & vy1 & vx1) ? p11[x1c] : 0.0f;

    float wx0 = 1.0f - rx, wy0 = 1.0f - ry, wz0 = 1.0f - rz;
    float a00 = fmaf(v001, rx, v000 * wx0);
    float a01 = fmaf(v011, rx, v010 * wx0);
    float a10 = fmaf(v101, rx, v100 * wx0);
    float a11 = fmaf(v111, rx, v110 * wx0);
    float b0  = fmaf(a01, ry, a00 * wy0);
    float b1  = fmaf(a11, ry, a10 * wy0);
    return fmaf(b1, rz, b0 * wz0);
}

// Shrink [lo,hi] (float d-range) to where g0 + s*d stays in
// (0.001, bound-1-0.001): both floor and floor+1 strictly interior.
__device__ __forceinline__ void axis_window(float g0, float s, float bound,
                                            float& lo, float& hi) {
    float upper = bound - 1.001f;
    if (fabsf(s) < 1e-6f) {
        if (!(g0 >= 0.001f && g0 <= upper)) { lo = 1e9f; hi = -1e9f; }
    } else {
        float inv = 1.0f / s;
        float a = (0.001f - g0) * inv;
        float b = (upper - g0) * inv;
        lo = fmaxf(lo, fminf(a, b));
        hi = fminf(hi, fmaxf(a, b));
    }
}

__global__ __launch_bounds__(256, 6)
void warp_kernel(const float* __restrict__ x,
                 const float* __restrict__ rot0, const float* __restrict__ rot1,
                 const float* __restrict__ rot2, const float* __restrict__ tr1,
                 const float* __restrict__ tr2,  const float* __restrict__ cp,
                 float* __restrict__ out) {
    __shared__ float M[12];
    int b  = blockIdx.y;                              // 0..BB-1
    int c  = blockIdx.z;                              // 0..DSPLIT-1

    if (threadIdx.x == 0) {
        float az = rot0[b], ay = rot1[b], ax = rot2[b];
        float cz, szs, cy, sys, cx, sxs;
        sincosf(az, &szs, &cz);
        sincosf(ay, &sys, &cy);
        sincosf(ax, &sxs, &cx);
        float R0 = cz*cy;
        float R1 = -szs*cx + cz*sys*sxs;
        float R2 =  szs*sxs + cz*sys*cx;
        float R3 = szs*cy;
        float R4 =  cz*cx + szs*sys*sxs;
        float R5 = -cz*sxs + szs*sys*cx;
        float R6 = -sys;
        float R7 = cy*sxs;
        float R8 = cy*cx;
        float t1 = tr1[b] * (float)HH;
        float t2 = tr2[b] * (float)WW;
        float c0 = cp[b*3+0], c1 = cp[b*3+1], c2 = cp[b*3+2];
        M[0]=R0; M[1]=R1; M[2]=R2;
        M[3]=R3; M[4]=R4; M[5]=R5;
        M[6]=R6; M[7]=R7; M[8]=R8;
        M[9]  = 0.0f - (R0*c0 + R1*c1 + R2*c2) + c0;
        M[10] = t1   - (R3*c0 + R4*c1 + R5*c2) + c1;
        M[11] = t2   - (R6*c0 + R7*c1 + R8*c2) + c2;
    }
    __syncthreads();

    int hw = blockIdx.x * blockDim.x + threadIdx.x;   // 0..HW-1
    int h  = hw / WW;
    int w  = hw - h * WW;
    int d0 = c * DCH;
    int dend = d0 + DCH;

    float fh = (float)h, fw = (float)w;
    float gz0 = fmaf(M[1], fh, fmaf(M[2], fw, M[9]));
    float gy0 = fmaf(M[4], fh, fmaf(M[5], fw, M[10]));
    float gx0 = fmaf(M[7], fh, fmaf(M[8], fw, M[11]));
    float sz = M[0], sy = M[3], sx = M[6];

    const float* __restrict__ vol = x + (size_t)b * VOL;
    float* __restrict__ outw = out + OFF_XWARP + (size_t)b * VOL + (size_t)hw;

    // Exact interior d-window: intersection of three per-axis intervals.
    float wlo = (float)d0, whi = (float)(dend - 1);
    axis_window(gz0, sz, (float)DD, wlo, whi);
    axis_window(gy0, sy, (float)HH, wlo, whi);
    axis_window(gx0, sx, (float)WW, wlo, whi);

    int flo, fhi;
    if (wlo > whi) { flo = dend; fhi = dend; }
    else {
        flo = max(d0,   (int)ceilf(wlo));
        fhi = min(dend, (int)floorf(whi) + 1);
        if (flo > fhi) { flo = dend; fhi = dend; }
    }

    float sum = 0.0f;
    int j = d0;

    for (; j < flo; ++j) {   // pre-window guarded (boundary band only)
        float fd = (float)j;
        float val = guarded_sample(vol,
            fmaf(fd, sz, gz0), fmaf(fd, sy, gy0), fmaf(fd, sx, gx0));
        outw[(size_t)j * HW] = val;
        sum += val;
    }

    // Interior fast loop with z-plane register reuse:
    // iz advances by 0/1 per step (sz ~ 0.96..1), iy/ix change every ~10
    // steps, so iter j+1's z0-plane corners usually equal iter j's z1-plane
    // corners. Cache them; predicated loads fill the rest.
    {
        int piz = -100000, piy = 0, pix = 0;
        float c00 = 0.f, c01 = 0.f, c10 = 0.f, c11 = 0.f;

        #pragma unroll 4
        for (; j < fhi; ++j) {
            float fd = (float)j;
            float gz = fmaf(fd, sz, gz0);
            float gy = fmaf(fd, sy, gy0);
            float gx = fmaf(fd, sx, gx0);

            int iz = (int)gz;
            int iy = (int)gy;
            int ix = (int)gx;
            float rz = gz - (float)iz;
            float ry = gy - (float)iy;
            float rx = gx - (float)ix;

            const float* p = vol + iz * HW + iy * WW + ix;

            // upper plane: always fresh (becomes next iter's cache)
            float v100 = p[HW];
            float v101 = p[HW + 1];
            float v110 = p[HW + WW];
            float v111 = p[HW + WW + 1];

            bool reuse = (iz == piz + 1) & (iy == piy) & (ix == pix);
            float v000 = reuse ? c00 : p[0];
            float v001 = reuse ? c01 : p[1];
            float v010 = reuse ? c10 : p[WW];
            float v011 = reuse ? c11 : p[WW + 1];

            c00 = v100; c01 = v101; c10 = v110; c11 = v111;
            piz = iz; piy = iy; pix = ix;

            float wx0 = 1.0f - rx, wy0 = 1.0f - ry, wz0 = 1.0f - rz;
            float a00 = fmaf(v001, rx, v000 * wx0);
            float a01 = fmaf(v011, rx, v010 * wx0);
            float a10 = fmaf(v101, rx, v100 * wx0);
            float a11 = fmaf(v111, rx, v110 * wx0);
            float b0  = fmaf(a01, ry, a00 * wy0);
            float b1  = fmaf(a11, ry, a10 * wy0);
            float val = fmaf(b1,  rz, b0  * wz0);

            outw[(size_t)j * HW] = val;
            sum += val;
        }
    }

    for (; j < dend; ++j) {  // post-window guarded
        float fd = (float)j;
        float val = guarded_sample(vol,
            fmaf(fd, sz, gz0), fmaf(fd, sy, gy0), fmaf(fd, sx, gx0));
        outw[(size_t)j * HW] = val;
        sum += val;
    }

    g_partial[(c * BB + b) * HW + hw] = sum;
}

// x_2d = mean of partials; y passthrough. float4-vectorized.
__global__ __launch_bounds__(256)
void reduce_kernel(const float* __restrict__ y, float* __restrict__ out) {
    int i = blockIdx.x * blockDim.x + threadIdx.x;   // 0..BHW/4-1
    if (i >= BHW / 4) return;
    int i4 = i * 4;
    int b  = i4 / HW;           // HW % 4 == 0 -> same b for all 4 lanes
    int hw = i4 - b * HW;

    float4 s = make_float4(0.f, 0.f, 0.f, 0.f);
    #pragma unroll
    for (int c = 0; c < DSPLIT; ++c) {
        const float4 p = *(const float4*)&g_partial[(c * BB + b) * HW + hw];
        s.x += p.x; s.y += p.y; s.z += p.z; s.w += p.w;
    }
    const float inv = 1.0f / (float)DD;
    s.x *= inv; s.y *= inv; s.z *= inv; s.w *= inv;
    *(float4*)&out[i4] = s;
    *(float4*)&out[OFF_Y + i4] = *(const float4*)&y[i4];
}

extern "C" void kernel_launch(void* const* d_in, const int* in_sizes, int n_in,
                              void* d_out, int out_size) {
    const float* x    = (const float*)d_in[0];
    const float* y    = (const float*)d_in[1];
    const float* rot0 = (const float*)d_in[2];
    const float* rot1 = (const float*)d_in[3];
    const float* rot2 = (const float*)d_in[4];
    const float* tr1  = (const float*)d_in[5];
    const float* tr2  = (const float*)d_in[6];
    const float* cp   = (const float*)d_in[7];
    float* out = (float*)d_out;

    dim3 grid(HW / 256, BB, DSPLIT);
    warp_kernel<<<grid, 256>>>(x, rot0, rot1, rot2, tr1, tr2, cp, out);
    reduce_kernel<<<(BHW / 4 + 255) / 256, 256>>>(y, out);
}